// round 14
// baseline (speedup 1.0000x reference)
#include <cuda_runtime.h>
#include <math_constants.h>

#define NN 100000
#define C  128
#define EMAX_E 500000
#define NEG_SLOPE 0.2f
#define SCAN_BLK 1024
#define NSCAN_BLKS ((NN + SCAN_BLK - 1) / SCAN_BLK)   // 98

// ---------------- scratch (device globals, no allocations allowed) ----------
__device__ float g_xl[NN * C];
__device__ float g_xr[NN * C];
__device__ float g_xres[NN * C];
__device__ float g_x1[NN * C];
__device__ int   g_rowptr[NN + 1];
__device__ int   g_cursor[NN];
__device__ int   g_blocksums[SCAN_BLK];
__device__ int   g_csr_src[EMAX_E];

// ---------------- TF32 tensor-core GEMM ------------------------------------
// Block tile 128x128, K=128. A panel resident; B staged in 64-row half-panels
// so SMEM = 101.4KB -> 2 CTAs/SM. 8 warps, warp tile 64x32 (proven R11 shape).
__device__ __forceinline__ unsigned f2tf32(float f) {
    unsigned r;
    asm("cvt.rna.tf32.f32 %0, %1;" : "=r"(r) : "f"(f));
    return r;
}

#define PSTRIDE 132                          // 128 + 4 pad (words)
#define SMEM_WORDS ((128 + 64) * PSTRIDE)    // A panel 128xK + B half-panel 64xN
#define SMEM_BYTES (SMEM_WORDS * 4)          // 101376

__global__ __launch_bounds__(256, 2) void gemm3_fused_kernel(
    const float* __restrict__ X,
    const float* __restrict__ Wl, const float* __restrict__ Wr,
    const float* __restrict__ Wres, const float* __restrict__ bias,
    float* __restrict__ Yl, float* __restrict__ Yr, float* __restrict__ Yres,
    int M)
{
    extern __shared__ unsigned sh[];
    unsigned* As = sh;                  // [128][PSTRIDE]
    unsigned* Bs = sh + 128 * PSTRIDE;  // [64][PSTRIDE]

    const int tid  = threadIdx.x;
    const int lane = tid & 31;
    const int wid  = tid >> 5;
    const int wr   = wid >> 2;      // 0..1 -> M offset wr*64
    const int wc   = wid & 3;       // 0..3 -> N offset wc*32
    const int gp   = lane >> 2;
    const int tg   = lane & 3;
    const int m0   = blockIdx.x * 128;

    // ---- stage full A panel (128 rows x 128 k) as tf32 ----
#pragma unroll
    for (int i = tid; i < 128 * 32; i += 256) {
        int row = i >> 5, c4 = i & 31;
        int gm = m0 + row;
        float4 v = (gm < M) ? ((const float4*)(X + (size_t)gm * 128))[c4]
                            : make_float4(0.f, 0.f, 0.f, 0.f);
        unsigned* p = &As[row * PSTRIDE + c4 * 4];
        p[0] = f2tf32(v.x); p[1] = f2tf32(v.y);
        p[2] = f2tf32(v.z); p[3] = f2tf32(v.w);
    }

    for (int which = 0; which < 3; which++) {
        const float* W = (which == 0) ? Wl : (which == 1) ? Wr : Wres;
        float* Y       = (which == 0) ? Yl : (which == 1) ? Yr : Yres;

        float acc[4][4][4];
#pragma unroll
        for (int mi = 0; mi < 4; mi++)
#pragma unroll
            for (int ni = 0; ni < 4; ni++)
#pragma unroll
                for (int r = 0; r < 4; r++) acc[mi][ni][r] = 0.f;

#pragma unroll
        for (int half = 0; half < 2; half++) {
            __syncthreads();   // A ready / prior readers of Bs done
            // ---- stage B half-panel: k-rows [half*64, half*64+64) ----
#pragma unroll
            for (int i = tid; i < 64 * 32; i += 256) {
                int row = i >> 5, c4 = i & 31;
                float4 v = ((const float4*)(W + (half * 64 + row) * 128))[c4];
                unsigned* p = &Bs[row * PSTRIDE + c4 * 4];
                p[0] = f2tf32(v.x); p[1] = f2tf32(v.y);
                p[2] = f2tf32(v.z); p[3] = f2tf32(v.w);
            }
            __syncthreads();

#pragma unroll 4
            for (int kk0 = 0; kk0 < 64; kk0 += 8) {
                int kk = half * 64 + kk0;     // A k-index
                unsigned a[4][4];
#pragma unroll
                for (int mi = 0; mi < 4; mi++) {
                    int mrow = wr * 64 + mi * 16 + gp;
                    a[mi][0] = As[(mrow    ) * PSTRIDE + kk + tg    ];
                    a[mi][1] = As[(mrow + 8) * PSTRIDE + kk + tg    ];
                    a[mi][2] = As[(mrow    ) * PSTRIDE + kk + tg + 4];
                    a[mi][3] = As[(mrow + 8) * PSTRIDE + kk + tg + 4];
                }
                unsigned b[4][2];
#pragma unroll
                for (int ni = 0; ni < 4; ni++) {
                    int ncol = wc * 32 + ni * 8 + gp;
                    b[ni][0] = Bs[(kk0 + tg    ) * PSTRIDE + ncol];
                    b[ni][1] = Bs[(kk0 + tg + 4) * PSTRIDE + ncol];
                }
#pragma unroll
                for (int mi = 0; mi < 4; mi++)
#pragma unroll
                    for (int ni = 0; ni < 4; ni++) {
                        asm volatile(
                            "mma.sync.aligned.m16n8k8.row.col.f32.tf32.tf32.f32 "
                            "{%0,%1,%2,%3}, {%4,%5,%6,%7}, {%8,%9}, {%0,%1,%2,%3};"
                            : "+f"(acc[mi][ni][0]), "+f"(acc[mi][ni][1]),
                              "+f"(acc[mi][ni][2]), "+f"(acc[mi][ni][3])
                            : "r"(a[mi][0]), "r"(a[mi][1]), "r"(a[mi][2]), "r"(a[mi][3]),
                              "r"(b[ni][0]), "r"(b[ni][1]));
                    }
            }
        }

        // ---- epilogue ----
#pragma unroll
        for (int mi = 0; mi < 4; mi++) {
#pragma unroll
            for (int ni = 0; ni < 4; ni++) {
                int row = m0 + wr * 64 + mi * 16 + gp;
                int col = wc * 32 + ni * 8 + tg * 2;
                float b0 = 0.f, b1 = 0.f;
                if (which == 2 && bias) { b0 = bias[col]; b1 = bias[col + 1]; }
                if (row < M) {
                    float2 v = make_float2(acc[mi][ni][0] + b0,
                                           acc[mi][ni][1] + b1);
                    *(float2*)&Y[(size_t)row * 128 + col] = v;
                }
                if (row + 8 < M) {
                    float2 v = make_float2(acc[mi][ni][2] + b0,
                                           acc[mi][ni][3] + b1);
                    *(float2*)&Y[(size_t)(row + 8) * 128 + col] = v;
                }
            }
        }
    }
}

// ================= CSR construction (once per call, shared by layers) =======
__global__ void deg_zero_kernel(int* __restrict__ deg)
{
    int i = blockIdx.x * blockDim.x + threadIdx.x;
    if (i < NN) deg[i] = 0;
}

__global__ void count_kernel(const int* __restrict__ dst, int* __restrict__ deg,
                             int E)
{
    int i = blockIdx.x * blockDim.x + threadIdx.x;
    if (i < E) atomicAdd(&deg[dst[i]], 1);
}

__global__ __launch_bounds__(SCAN_BLK) void scan1_kernel(
    const int* __restrict__ deg, int* __restrict__ pref,
    int* __restrict__ blockSums)
{
    __shared__ int sm[SCAN_BLK];
    int tid = threadIdx.x;
    int i = blockIdx.x * SCAN_BLK + tid;
    int v = (i < NN) ? deg[i] : 0;
    sm[tid] = v;
    __syncthreads();
#pragma unroll
    for (int off = 1; off < SCAN_BLK; off <<= 1) {
        int t = (tid >= off) ? sm[tid - off] : 0;
        __syncthreads();
        sm[tid] += t;
        __syncthreads();
    }
    if (i < NN) pref[i] = sm[tid] - v;
    if (tid == SCAN_BLK - 1) blockSums[blockIdx.x] = sm[tid];
}

__global__ __launch_bounds__(128) void scan2_kernel(int* __restrict__ blockSums)
{
    __shared__ int sm[128];
    int tid = threadIdx.x;
    int v = (tid < NSCAN_BLKS) ? blockSums[tid] : 0;
    sm[tid] = v;
    __syncthreads();
#pragma unroll
    for (int off = 1; off < 128; off <<= 1) {
        int t = (tid >= off) ? sm[tid - off] : 0;
        __syncthreads();
        sm[tid] += t;
        __syncthreads();
    }
    if (tid < NSCAN_BLKS) blockSums[tid] = sm[tid] - v;
}

__global__ void scan3_kernel(const int* __restrict__ pref,
                             const int* __restrict__ blockSums,
                             int* __restrict__ rowptr, int* __restrict__ cursor,
                             int E)
{
    int i = blockIdx.x * blockDim.x + threadIdx.x;
    if (i < NN) {
        int r = pref[i] + blockSums[i >> 10];
        rowptr[i] = r;
        cursor[i] = r;
    }
    if (i == 0) rowptr[NN] = E;
}

__global__ void scatter_kernel(const int* __restrict__ src,
                               const int* __restrict__ dst,
                               int* __restrict__ cursor,
                               int* __restrict__ csr_src, int E)
{
    int i = blockIdx.x * blockDim.x + threadIdx.x;
    if (i < E) {
        int p = atomicAdd(&cursor[dst[i]], 1);
        csr_src[p] = src[i];
    }
}

// ================= fused node aggregation ===================================
// 8-lane groups: 4 nodes per warp. Each lane owns 16 channels (4 x float4).
// 3-level butterfly within the group; 4 independent edge chains per warp.
__device__ __forceinline__ float lrelu(float v)
{
    return v > 0.f ? v : NEG_SLOPE * v;
}

__global__ __launch_bounds__(256) void node_agg_kernel(
    const float* __restrict__ xl, const float* __restrict__ xr,
    const float* __restrict__ xres, const float* __restrict__ att,
    const int* __restrict__ rowptr, const int* __restrict__ csr_src,
    float* __restrict__ out)
{
    int t = blockIdx.x * blockDim.x + threadIdx.x;
    int warp = t >> 5;
    int lane = threadIdx.x & 31;
    int g = lane >> 3;            // group 0..3
    int q = lane & 7;             // sublane 0..7
    int n = warp * 4 + g;
    if (n >= NN) return;

    unsigned gmask = 0xFFu << (g * 8);
    int cbase = q * 16;           // this lane's 16-channel base

    float4 at4[4], r4[4];
#pragma unroll
    for (int i = 0; i < 4; i++) {
        at4[i] = *(const float4*)&att[cbase + i * 4];
        r4[i]  = *(const float4*)&xr[(size_t)n * 128 + cbase + i * 4];
    }

    int beg = rowptr[n];
    int end = rowptr[n + 1];

    float4 acc4[4];
#pragma unroll
    for (int i = 0; i < 4; i++) acc4[i] = make_float4(0.f, 0.f, 0.f, 0.f);
    float den = 0.f;

    for (int j = beg; j < end; j++) {
        int s = __ldg(&csr_src[j]);
        float4 a4[4];
#pragma unroll
        for (int i = 0; i < 4; i++)
            a4[i] = *(const float4*)&xl[(size_t)s * 128 + cbase + i * 4];

        float p = 0.f;
#pragma unroll
        for (int i = 0; i < 4; i++) {
            p += lrelu(a4[i].x + r4[i].x) * at4[i].x
               + lrelu(a4[i].y + r4[i].y) * at4[i].y
               + lrelu(a4[i].z + r4[i].z) * at4[i].z
               + lrelu(a4[i].w + r4[i].w) * at4[i].w;
        }
        // 3-level butterfly within the 8-lane group
        p += __shfl_xor_sync(gmask, p, 4);
        p += __shfl_xor_sync(gmask, p, 2);
        p += __shfl_xor_sync(gmask, p, 1);

        float ex = __expf(p);
#pragma unroll
        for (int i = 0; i < 4; i++) {
            acc4[i].x += ex * a4[i].x;
            acc4[i].y += ex * a4[i].y;
            acc4[i].z += ex * a4[i].z;
            acc4[i].w += ex * a4[i].w;
        }
        den += ex;
    }

    float inv = 1.f / fmaxf(den, 1e-16f);
#pragma unroll
    for (int i = 0; i < 4; i++) {
        float4 rs = *(const float4*)&xres[(size_t)n * 128 + cbase + i * 4];
        float4 o;
        o.x = fmaxf(acc4[i].x * inv + rs.x, 0.f);
        o.y = fmaxf(acc4[i].y * inv + rs.y, 0.f);
        o.z = fmaxf(acc4[i].z * inv + rs.z, 0.f);
        o.w = fmaxf(acc4[i].w * inv + rs.w, 0.f);
        *(float4*)&out[(size_t)n * 128 + cbase + i * 4] = o;
    }
}

// ---------------- host orchestration ----------------------------------------
extern "C" void kernel_launch(void* const* d_in, const int* in_sizes, int n_in,
                              void* d_out, int out_size)
{
    const float* x    = (const float*)d_in[0];
    const int* eidx   = (const int*)d_in[1];
    const float* Wl1  = (const float*)d_in[2];
    const float* Wr1  = (const float*)d_in[3];
    const float* att1 = (const float*)d_in[4];
    const float* Wres1= (const float*)d_in[5];
    const float* b1   = (const float*)d_in[6];
    const float* Wl2  = (const float*)d_in[7];
    const float* Wr2  = (const float*)d_in[8];
    const float* att2 = (const float*)d_in[9];
    const float* Wres2= (const float*)d_in[10];
    const float* b2   = (const float*)d_in[11];

    int E = in_sizes[1] / 2;
    const int* src = eidx;
    const int* dst = eidx + E;

    float *xl, *xr, *xres, *x1;
    int *rowptr, *cursor, *blocksums, *csr_src;
    cudaGetSymbolAddress((void**)&xl, g_xl);
    cudaGetSymbolAddress((void**)&xr, g_xr);
    cudaGetSymbolAddress((void**)&xres, g_xres);
    cudaGetSymbolAddress((void**)&x1, g_x1);
    cudaGetSymbolAddress((void**)&rowptr, g_rowptr);
    cudaGetSymbolAddress((void**)&cursor, g_cursor);
    cudaGetSymbolAddress((void**)&blocksums, g_blocksums);
    cudaGetSymbolAddress((void**)&csr_src, g_csr_src);

    static bool attr_set = false;
    if (!attr_set) {
        cudaFuncSetAttribute(gemm3_fused_kernel,
                             cudaFuncAttributeMaxDynamicSharedMemorySize,
                             SMEM_BYTES);
        attr_set = true;
    }

    // ---- CSR build (exact R11 sequence) ----
    deg_zero_kernel<<<(NN + 255) / 256, 256>>>(rowptr);
    count_kernel<<<(E + 255) / 256, 256>>>(dst, rowptr, E);
    scan1_kernel<<<NSCAN_BLKS, SCAN_BLK>>>(rowptr, cursor, blocksums);
    scan2_kernel<<<1, 128>>>(blocksums);
    scan3_kernel<<<(NN + 255) / 256, 256>>>(cursor, blocksums, rowptr, cursor, E);
    scatter_kernel<<<(E + 255) / 256, 256>>>(src, dst, cursor, csr_src, E);

    int gemmBlocks = (NN + 127) / 128;
    int aggWarps   = (NN + 3) / 4;                    // 4 nodes per warp
    int aggBlocks  = (aggWarps * 32 + 255) / 256;

    // ---- layer 1 ----
    gemm3_fused_kernel<<<gemmBlocks, 256, SMEM_BYTES>>>(
        x, Wl1, Wr1, Wres1, b1, xl, xr, xres, NN);
    node_agg_kernel<<<aggBlocks, 256>>>(xl, xr, xres, att1, rowptr, csr_src, x1);

    // ---- layer 2 ----
    gemm3_fused_kernel<<<gemmBlocks, 256, SMEM_BYTES>>>(
        x1, Wl2, Wr2, Wres2, b2, xl, xr, xres, NN);
    node_agg_kernel<<<aggBlocks, 256>>>(xl, xr, xres, att2, rowptr, csr_src,
                                        (float*)d_out);
}

// round 15
// speedup vs baseline: 1.0627x; 1.0627x over previous
#include <cuda_runtime.h>
#include <math_constants.h>

#define NN 100000
#define C  128
#define EMAX_E 500000
#define NEG_SLOPE 0.2f
#define SCAN_BLK 1024
#define NSCAN_BLKS ((NN + SCAN_BLK - 1) / SCAN_BLK)   // 98

// ---------------- scratch (device globals, no allocations allowed) ----------
__device__ float g_xl[NN * C];
__device__ float g_xr[NN * C];
__device__ float g_xres[NN * C];
__device__ float g_x1[NN * C];
__device__ int   g_rowptr[NN + 1];
__device__ int   g_cursor[NN];
__device__ int   g_blocksums[SCAN_BLK];
__device__ int   g_csr_src[EMAX_E];

// ---------------- TF32 tensor-core GEMM ------------------------------------
// Block tile 128x128, K=128. A panel resident; B staged in 64-row half-panels
// so SMEM = 101.4KB -> 2 CTAs/SM. 8 warps, warp tile 64x32 (proven R11 shape).
__device__ __forceinline__ unsigned f2tf32(float f) {
    unsigned r;
    asm("cvt.rna.tf32.f32 %0, %1;" : "=r"(r) : "f"(f));
    return r;
}

#define PSTRIDE 132                          // 128 + 4 pad (words)
#define SMEM_WORDS ((128 + 64) * PSTRIDE)    // A panel 128xK + B half-panel 64xN
#define SMEM_BYTES (SMEM_WORDS * 4)          // 101376

__global__ __launch_bounds__(256, 2) void gemm3_fused_kernel(
    const float* __restrict__ X,
    const float* __restrict__ Wl, const float* __restrict__ Wr,
    const float* __restrict__ Wres, const float* __restrict__ bias,
    float* __restrict__ Yl, float* __restrict__ Yr, float* __restrict__ Yres,
    int M)
{
    extern __shared__ unsigned sh[];
    unsigned* As = sh;                  // [128][PSTRIDE]
    unsigned* Bs = sh + 128 * PSTRIDE;  // [64][PSTRIDE]

    const int tid  = threadIdx.x;
    const int lane = tid & 31;
    const int wid  = tid >> 5;
    const int wr   = wid >> 2;      // 0..1 -> M offset wr*64
    const int wc   = wid & 3;       // 0..3 -> N offset wc*32
    const int gp   = lane >> 2;
    const int tg   = lane & 3;
    const int m0   = blockIdx.x * 128;

    // ---- stage full A panel (128 rows x 128 k) as tf32 ----
#pragma unroll
    for (int i = tid; i < 128 * 32; i += 256) {
        int row = i >> 5, c4 = i & 31;
        int gm = m0 + row;
        float4 v = (gm < M) ? ((const float4*)(X + (size_t)gm * 128))[c4]
                            : make_float4(0.f, 0.f, 0.f, 0.f);
        unsigned* p = &As[row * PSTRIDE + c4 * 4];
        p[0] = f2tf32(v.x); p[1] = f2tf32(v.y);
        p[2] = f2tf32(v.z); p[3] = f2tf32(v.w);
    }

    for (int which = 0; which < 3; which++) {
        const float* W = (which == 0) ? Wl : (which == 1) ? Wr : Wres;
        float* Y       = (which == 0) ? Yl : (which == 1) ? Yr : Yres;

        float acc[4][4][4];
#pragma unroll
        for (int mi = 0; mi < 4; mi++)
#pragma unroll
            for (int ni = 0; ni < 4; ni++)
#pragma unroll
                for (int r = 0; r < 4; r++) acc[mi][ni][r] = 0.f;

#pragma unroll
        for (int half = 0; half < 2; half++) {
            __syncthreads();   // A ready / prior readers of Bs done
            // ---- stage B half-panel: k-rows [half*64, half*64+64) ----
#pragma unroll
            for (int i = tid; i < 64 * 32; i += 256) {
                int row = i >> 5, c4 = i & 31;
                float4 v = ((const float4*)(W + (half * 64 + row) * 128))[c4];
                unsigned* p = &Bs[row * PSTRIDE + c4 * 4];
                p[0] = f2tf32(v.x); p[1] = f2tf32(v.y);
                p[2] = f2tf32(v.z); p[3] = f2tf32(v.w);
            }
            __syncthreads();

#pragma unroll 4
            for (int kk0 = 0; kk0 < 64; kk0 += 8) {
                int kk = half * 64 + kk0;     // A k-index
                unsigned a[4][4];
#pragma unroll
                for (int mi = 0; mi < 4; mi++) {
                    int mrow = wr * 64 + mi * 16 + gp;
                    a[mi][0] = As[(mrow    ) * PSTRIDE + kk + tg    ];
                    a[mi][1] = As[(mrow + 8) * PSTRIDE + kk + tg    ];
                    a[mi][2] = As[(mrow    ) * PSTRIDE + kk + tg + 4];
                    a[mi][3] = As[(mrow + 8) * PSTRIDE + kk + tg + 4];
                }
                unsigned b[4][2];
#pragma unroll
                for (int ni = 0; ni < 4; ni++) {
                    int ncol = wc * 32 + ni * 8 + gp;
                    b[ni][0] = Bs[(kk0 + tg    ) * PSTRIDE + ncol];
                    b[ni][1] = Bs[(kk0 + tg + 4) * PSTRIDE + ncol];
                }
#pragma unroll
                for (int mi = 0; mi < 4; mi++)
#pragma unroll
                    for (int ni = 0; ni < 4; ni++) {
                        asm volatile(
                            "mma.sync.aligned.m16n8k8.row.col.f32.tf32.tf32.f32 "
                            "{%0,%1,%2,%3}, {%4,%5,%6,%7}, {%8,%9}, {%0,%1,%2,%3};"
                            : "+f"(acc[mi][ni][0]), "+f"(acc[mi][ni][1]),
                              "+f"(acc[mi][ni][2]), "+f"(acc[mi][ni][3])
                            : "r"(a[mi][0]), "r"(a[mi][1]), "r"(a[mi][2]), "r"(a[mi][3]),
                              "r"(b[ni][0]), "r"(b[ni][1]));
                    }
            }
        }

        // ---- epilogue ----
#pragma unroll
        for (int mi = 0; mi < 4; mi++) {
#pragma unroll
            for (int ni = 0; ni < 4; ni++) {
                int row = m0 + wr * 64 + mi * 16 + gp;
                int col = wc * 32 + ni * 8 + tg * 2;
                float b0 = 0.f, b1 = 0.f;
                if (which == 2 && bias) { b0 = bias[col]; b1 = bias[col + 1]; }
                if (row < M) {
                    float2 v = make_float2(acc[mi][ni][0] + b0,
                                           acc[mi][ni][1] + b1);
                    *(float2*)&Y[(size_t)row * 128 + col] = v;
                }
                if (row + 8 < M) {
                    float2 v = make_float2(acc[mi][ni][2] + b0,
                                           acc[mi][ni][3] + b1);
                    *(float2*)&Y[(size_t)(row + 8) * 128 + col] = v;
                }
            }
        }
    }
}

// ================= CSR construction (once per call, shared by layers) =======
__global__ void count_kernel(const int* __restrict__ dst, int* __restrict__ deg,
                             int E)
{
    int i = blockIdx.x * blockDim.x + threadIdx.x;
    if (i < E) atomicAdd(&deg[dst[i]], 1);
}

__global__ __launch_bounds__(SCAN_BLK) void scan1_kernel(
    const int* __restrict__ deg, int* __restrict__ pref,
    int* __restrict__ blockSums)
{
    __shared__ int sm[SCAN_BLK];
    int tid = threadIdx.x;
    int i = blockIdx.x * SCAN_BLK + tid;
    int v = (i < NN) ? deg[i] : 0;
    sm[tid] = v;
    __syncthreads();
#pragma unroll
    for (int off = 1; off < SCAN_BLK; off <<= 1) {
        int t = (tid >= off) ? sm[tid - off] : 0;
        __syncthreads();
        sm[tid] += t;
        __syncthreads();
    }
    if (i < NN) pref[i] = sm[tid] - v;
    if (tid == SCAN_BLK - 1) blockSums[blockIdx.x] = sm[tid];
}

__global__ __launch_bounds__(128) void scan2_kernel(int* __restrict__ blockSums)
{
    __shared__ int sm[128];
    int tid = threadIdx.x;
    int v = (tid < NSCAN_BLKS) ? blockSums[tid] : 0;
    sm[tid] = v;
    __syncthreads();
#pragma unroll
    for (int off = 1; off < 128; off <<= 1) {
        int t = (tid >= off) ? sm[tid - off] : 0;
        __syncthreads();
        sm[tid] += t;
        __syncthreads();
    }
    if (tid < NSCAN_BLKS) blockSums[tid] = sm[tid] - v;
}

__global__ void scan3_kernel(const int* __restrict__ pref,
                             const int* __restrict__ blockSums,
                             int* __restrict__ rowptr, int* __restrict__ cursor,
                             int E)
{
    int i = blockIdx.x * blockDim.x + threadIdx.x;
    if (i < NN) {
        int r = pref[i] + blockSums[i >> 10];
        rowptr[i] = r;
        cursor[i] = r;
    }
    if (i == 0) rowptr[NN] = E;
}

__global__ void scatter_kernel(const int* __restrict__ src,
                               const int* __restrict__ dst,
                               int* __restrict__ cursor,
                               int* __restrict__ csr_src, int E)
{
    int i = blockIdx.x * blockDim.x + threadIdx.x;
    if (i < E) {
        int p = atomicAdd(&cursor[dst[i]], 1);
        csr_src[p] = src[i];
    }
}

// ================= fused node aggregation ===================================
// Warp-per-node, unroll2 (R11 local optimum) + next-pair index prefetch.
__device__ __forceinline__ float lrelu(float v)
{
    return v > 0.f ? v : NEG_SLOPE * v;
}

__device__ __forceinline__ float edge_logit(float4 a, float4 r, float4 at)
{
    return lrelu(a.x + r.x) * at.x + lrelu(a.y + r.y) * at.y
         + lrelu(a.z + r.z) * at.z + lrelu(a.w + r.w) * at.w;
}

__global__ __launch_bounds__(256) void node_agg_kernel(
    const float* __restrict__ xl, const float* __restrict__ xr,
    const float* __restrict__ xres, const float* __restrict__ att,
    const int* __restrict__ rowptr, const int* __restrict__ csr_src,
    float* __restrict__ out)
{
    int n = (blockIdx.x * blockDim.x + threadIdx.x) >> 5;
    int lane = threadIdx.x & 31;
    if (n >= NN) return;

    float4 at = *(const float4*)&att[lane * 4];
    float4 r  = *(const float4*)&xr[(size_t)n * 128 + lane * 4];

    int beg = rowptr[n];
    int end = rowptr[n + 1];

    float4 acc = make_float4(0.f, 0.f, 0.f, 0.f);
    float den = 0.f;

    // prefetched indices for the current pair
    int sA = 0, sB = 0;
    if (beg < end) sA = __ldg(&csr_src[beg]);
    if (beg + 1 < end) sB = __ldg(&csr_src[beg + 1]);

    int j = beg;
    for (; j + 1 < end; j += 2) {
        int s0 = sA, s1 = sB;
        // prefetch next pair's indices before the gathers stall this iteration
        if (j + 3 < end) {
            sA = __ldg(&csr_src[j + 2]);
            sB = __ldg(&csr_src[j + 3]);
        } else if (j + 2 < end) {
            sA = __ldg(&csr_src[j + 2]);
        }

        float4 a0 = *(const float4*)&xl[(size_t)s0 * 128 + lane * 4];
        float4 a1 = *(const float4*)&xl[(size_t)s1 * 128 + lane * 4];

        float p0 = edge_logit(a0, r, at);
        float p1 = edge_logit(a1, r, at);

#pragma unroll
        for (int off = 16; off > 0; off >>= 1) {
            p0 += __shfl_xor_sync(0xFFFFFFFFu, p0, off);
            p1 += __shfl_xor_sync(0xFFFFFFFFu, p1, off);
        }
        float ex0 = __expf(p0);
        float ex1 = __expf(p1);

        acc.x += ex0 * a0.x + ex1 * a1.x;
        acc.y += ex0 * a0.y + ex1 * a1.y;
        acc.z += ex0 * a0.z + ex1 * a1.z;
        acc.w += ex0 * a0.w + ex1 * a1.w;
        den += ex0 + ex1;
    }
    if (j < end) {
        int s = sA;
        float4 a = *(const float4*)&xl[(size_t)s * 128 + lane * 4];
        float p = edge_logit(a, r, at);
#pragma unroll
        for (int off = 16; off > 0; off >>= 1)
            p += __shfl_xor_sync(0xFFFFFFFFu, p, off);
        float ex = __expf(p);
        acc.x += ex * a.x; acc.y += ex * a.y;
        acc.z += ex * a.z; acc.w += ex * a.w;
        den += ex;
    }

    float inv = 1.f / fmaxf(den, 1e-16f);
    float4 rs = *(const float4*)&xres[(size_t)n * 128 + lane * 4];
    float4 o;
    o.x = fmaxf(acc.x * inv + rs.x, 0.f);
    o.y = fmaxf(acc.y * inv + rs.y, 0.f);
    o.z = fmaxf(acc.z * inv + rs.z, 0.f);
    o.w = fmaxf(acc.w * inv + rs.w, 0.f);
    *(float4*)&out[(size_t)n * 128 + lane * 4] = o;
}

// ---------------- host orchestration ----------------------------------------
extern "C" void kernel_launch(void* const* d_in, const int* in_sizes, int n_in,
                              void* d_out, int out_size)
{
    const float* x    = (const float*)d_in[0];
    const int* eidx   = (const int*)d_in[1];
    const float* Wl1  = (const float*)d_in[2];
    const float* Wr1  = (const float*)d_in[3];
    const float* att1 = (const float*)d_in[4];
    const float* Wres1= (const float*)d_in[5];
    const float* b1   = (const float*)d_in[6];
    const float* Wl2  = (const float*)d_in[7];
    const float* Wr2  = (const float*)d_in[8];
    const float* att2 = (const float*)d_in[9];
    const float* Wres2= (const float*)d_in[10];
    const float* b2   = (const float*)d_in[11];

    int E = in_sizes[1] / 2;
    const int* src = eidx;
    const int* dst = eidx + E;

    float *xl, *xr, *xres, *x1;
    int *rowptr, *cursor, *blocksums, *csr_src;
    cudaGetSymbolAddress((void**)&xl, g_xl);
    cudaGetSymbolAddress((void**)&xr, g_xr);
    cudaGetSymbolAddress((void**)&xres, g_xres);
    cudaGetSymbolAddress((void**)&x1, g_x1);
    cudaGetSymbolAddress((void**)&rowptr, g_rowptr);
    cudaGetSymbolAddress((void**)&cursor, g_cursor);
    cudaGetSymbolAddress((void**)&blocksums, g_blocksums);
    cudaGetSymbolAddress((void**)&csr_src, g_csr_src);

    static bool attr_set = false;
    if (!attr_set) {
        cudaFuncSetAttribute(gemm3_fused_kernel,
                             cudaFuncAttributeMaxDynamicSharedMemorySize,
                             SMEM_BYTES);
        attr_set = true;
    }

    // ---- CSR build ----
    cudaMemsetAsync(rowptr, 0, NN * sizeof(int), 0);
    count_kernel<<<(E + 255) / 256, 256>>>(dst, rowptr, E);
    scan1_kernel<<<NSCAN_BLKS, SCAN_BLK>>>(rowptr, cursor, blocksums);
    scan2_kernel<<<1, 128>>>(blocksums);
    scan3_kernel<<<(NN + 255) / 256, 256>>>(cursor, blocksums, rowptr, cursor, E);
    scatter_kernel<<<(E + 255) / 256, 256>>>(src, dst, cursor, csr_src, E);

    int gemmBlocks = (NN + 127) / 128;
    int nodeBlocks = (NN * 32 + 255) / 256;

    // ---- layer 1 ----
    gemm3_fused_kernel<<<gemmBlocks, 256, SMEM_BYTES>>>(
        x, Wl1, Wr1, Wres1, b1, xl, xr, xres, NN);
    node_agg_kernel<<<nodeBlocks, 256>>>(xl, xr, xres, att1, rowptr, csr_src, x1);

    // ---- layer 2 ----
    gemm3_fused_kernel<<<gemmBlocks, 256, SMEM_BYTES>>>(
        x1, Wl2, Wr2, Wres2, b2, xl, xr, xres, NN);
    node_agg_kernel<<<nodeBlocks, 256>>>(xl, xr, xres, att2, rowptr, csr_src,
                                         (float*)d_out);
}

// round 16
// speedup vs baseline: 1.1146x; 1.0488x over previous
#include <cuda_runtime.h>
#include <math_constants.h>

#define NN 100000
#define C  128
#define EMAX_E 500000
#define NEG_SLOPE 0.2f
#define SCAN_BLK 1024
#define NSCAN_BLKS ((NN + SCAN_BLK - 1) / SCAN_BLK)   // 98

// ---------------- scratch (device globals, no allocations allowed) ----------
__device__ float g_xl[NN * C];
__device__ float g_xr[NN * C];
__device__ float g_xres[NN * C];
__device__ float g_x1[NN * C];
__device__ int   g_rowptr[NN + 1];
__device__ int   g_cursor[NN];
__device__ int   g_blocksums[SCAN_BLK];
__device__ int   g_csr_src[EMAX_E];

// ---------------- TF32 tensor-core GEMM ------------------------------------
// Block tile 128x128, K=128. A panel resident; B staged in 64-row half-panels
// so SMEM = 101.4KB -> 2 CTAs/SM. 8 warps, warp tile 64x32 (proven R11 shape).
__device__ __forceinline__ unsigned f2tf32(float f) {
    unsigned r;
    asm("cvt.rna.tf32.f32 %0, %1;" : "=r"(r) : "f"(f));
    return r;
}

#define PSTRIDE 132                          // 128 + 4 pad (words)
#define SMEM_WORDS ((128 + 64) * PSTRIDE)    // A panel 128xK + B half-panel 64xN
#define SMEM_BYTES (SMEM_WORDS * 4)          // 101376

__global__ __launch_bounds__(256, 2) void gemm3_fused_kernel(
    const float* __restrict__ X,
    const float* __restrict__ Wl, const float* __restrict__ Wr,
    const float* __restrict__ Wres, const float* __restrict__ bias,
    float* __restrict__ Yl, float* __restrict__ Yr, float* __restrict__ Yres,
    int M)
{
    extern __shared__ unsigned sh[];
    unsigned* As = sh;                  // [128][PSTRIDE]
    unsigned* Bs = sh + 128 * PSTRIDE;  // [64][PSTRIDE]

    const int tid  = threadIdx.x;
    const int lane = tid & 31;
    const int wid  = tid >> 5;
    const int wr   = wid >> 2;      // 0..1 -> M offset wr*64
    const int wc   = wid & 3;       // 0..3 -> N offset wc*32
    const int gp   = lane >> 2;
    const int tg   = lane & 3;
    const int m0   = blockIdx.x * 128;

    // ---- stage full A panel (128 rows x 128 k) as tf32 ----
#pragma unroll
    for (int i = tid; i < 128 * 32; i += 256) {
        int row = i >> 5, c4 = i & 31;
        int gm = m0 + row;
        float4 v = (gm < M) ? ((const float4*)(X + (size_t)gm * 128))[c4]
                            : make_float4(0.f, 0.f, 0.f, 0.f);
        unsigned* p = &As[row * PSTRIDE + c4 * 4];
        p[0] = f2tf32(v.x); p[1] = f2tf32(v.y);
        p[2] = f2tf32(v.z); p[3] = f2tf32(v.w);
    }

    for (int which = 0; which < 3; which++) {
        const float* W = (which == 0) ? Wl : (which == 1) ? Wr : Wres;
        float* Y       = (which == 0) ? Yl : (which == 1) ? Yr : Yres;

        float acc[4][4][4];
#pragma unroll
        for (int mi = 0; mi < 4; mi++)
#pragma unroll
            for (int ni = 0; ni < 4; ni++)
#pragma unroll
                for (int r = 0; r < 4; r++) acc[mi][ni][r] = 0.f;

#pragma unroll
        for (int half = 0; half < 2; half++) {
            __syncthreads();   // A ready / prior readers of Bs done
            // ---- stage B half-panel: k-rows [half*64, half*64+64) ----
#pragma unroll
            for (int i = tid; i < 64 * 32; i += 256) {
                int row = i >> 5, c4 = i & 31;
                float4 v = ((const float4*)(W + (half * 64 + row) * 128))[c4];
                unsigned* p = &Bs[row * PSTRIDE + c4 * 4];
                p[0] = f2tf32(v.x); p[1] = f2tf32(v.y);
                p[2] = f2tf32(v.z); p[3] = f2tf32(v.w);
            }
            __syncthreads();

#pragma unroll 4
            for (int kk0 = 0; kk0 < 64; kk0 += 8) {
                int kk = half * 64 + kk0;     // A k-index
                unsigned a[4][4];
#pragma unroll
                for (int mi = 0; mi < 4; mi++) {
                    int mrow = wr * 64 + mi * 16 + gp;
                    a[mi][0] = As[(mrow    ) * PSTRIDE + kk + tg    ];
                    a[mi][1] = As[(mrow + 8) * PSTRIDE + kk + tg    ];
                    a[mi][2] = As[(mrow    ) * PSTRIDE + kk + tg + 4];
                    a[mi][3] = As[(mrow + 8) * PSTRIDE + kk + tg + 4];
                }
                unsigned b[4][2];
#pragma unroll
                for (int ni = 0; ni < 4; ni++) {
                    int ncol = wc * 32 + ni * 8 + gp;
                    b[ni][0] = Bs[(kk0 + tg    ) * PSTRIDE + ncol];
                    b[ni][1] = Bs[(kk0 + tg + 4) * PSTRIDE + ncol];
                }
#pragma unroll
                for (int mi = 0; mi < 4; mi++)
#pragma unroll
                    for (int ni = 0; ni < 4; ni++) {
                        asm volatile(
                            "mma.sync.aligned.m16n8k8.row.col.f32.tf32.tf32.f32 "
                            "{%0,%1,%2,%3}, {%4,%5,%6,%7}, {%8,%9}, {%0,%1,%2,%3};"
                            : "+f"(acc[mi][ni][0]), "+f"(acc[mi][ni][1]),
                              "+f"(acc[mi][ni][2]), "+f"(acc[mi][ni][3])
                            : "r"(a[mi][0]), "r"(a[mi][1]), "r"(a[mi][2]), "r"(a[mi][3]),
                              "r"(b[ni][0]), "r"(b[ni][1]));
                    }
            }
        }

        // ---- epilogue ----
#pragma unroll
        for (int mi = 0; mi < 4; mi++) {
#pragma unroll
            for (int ni = 0; ni < 4; ni++) {
                int row = m0 + wr * 64 + mi * 16 + gp;
                int col = wc * 32 + ni * 8 + tg * 2;
                float b0 = 0.f, b1 = 0.f;
                if (which == 2 && bias) { b0 = bias[col]; b1 = bias[col + 1]; }
                if (row < M) {
                    float2 v = make_float2(acc[mi][ni][0] + b0,
                                           acc[mi][ni][1] + b1);
                    *(float2*)&Y[(size_t)row * 128 + col] = v;
                }
                if (row + 8 < M) {
                    float2 v = make_float2(acc[mi][ni][2] + b0,
                                           acc[mi][ni][3] + b1);
                    *(float2*)&Y[(size_t)(row + 8) * 128 + col] = v;
                }
            }
        }
    }
}

// ================= CSR construction (once per call, shared by layers) =======
__global__ void deg_zero_kernel(int* __restrict__ deg)
{
    int i = blockIdx.x * blockDim.x + threadIdx.x;
    if (i < NN) deg[i] = 0;
}

__global__ void count_kernel(const int* __restrict__ dst, int* __restrict__ deg,
                             int E)
{
    int i = blockIdx.x * blockDim.x + threadIdx.x;
    if (i < E) atomicAdd(&deg[dst[i]], 1);
}

__global__ __launch_bounds__(SCAN_BLK) void scan1_kernel(
    const int* __restrict__ deg, int* __restrict__ pref,
    int* __restrict__ blockSums)
{
    __shared__ int sm[SCAN_BLK];
    int tid = threadIdx.x;
    int i = blockIdx.x * SCAN_BLK + tid;
    int v = (i < NN) ? deg[i] : 0;
    sm[tid] = v;
    __syncthreads();
#pragma unroll
    for (int off = 1; off < SCAN_BLK; off <<= 1) {
        int t = (tid >= off) ? sm[tid - off] : 0;
        __syncthreads();
        sm[tid] += t;
        __syncthreads();
    }
    if (i < NN) pref[i] = sm[tid] - v;
    if (tid == SCAN_BLK - 1) blockSums[blockIdx.x] = sm[tid];
}

__global__ __launch_bounds__(128) void scan2_kernel(int* __restrict__ blockSums)
{
    __shared__ int sm[128];
    int tid = threadIdx.x;
    int v = (tid < NSCAN_BLKS) ? blockSums[tid] : 0;
    sm[tid] = v;
    __syncthreads();
#pragma unroll
    for (int off = 1; off < 128; off <<= 1) {
        int t = (tid >= off) ? sm[tid - off] : 0;
        __syncthreads();
        sm[tid] += t;
        __syncthreads();
    }
    if (tid < NSCAN_BLKS) blockSums[tid] = sm[tid] - v;
}

__global__ void scan3_kernel(const int* __restrict__ pref,
                             const int* __restrict__ blockSums,
                             int* __restrict__ rowptr, int* __restrict__ cursor,
                             int E)
{
    int i = blockIdx.x * blockDim.x + threadIdx.x;
    if (i < NN) {
        int r = pref[i] + blockSums[i >> 10];
        rowptr[i] = r;
        cursor[i] = r;
    }
    if (i == 0) rowptr[NN] = E;
}

__global__ void scatter_kernel(const int* __restrict__ src,
                               const int* __restrict__ dst,
                               int* __restrict__ cursor,
                               int* __restrict__ csr_src, int E)
{
    int i = blockIdx.x * blockDim.x + threadIdx.x;
    if (i < E) {
        int p = atomicAdd(&cursor[dst[i]], 1);
        csr_src[p] = src[i];
    }
}

// ================= fused node aggregation ===================================
__device__ __forceinline__ float lrelu(float v)
{
    return v > 0.f ? v : NEG_SLOPE * v;
}

__device__ __forceinline__ float edge_logit(float4 a, float4 r, float4 at)
{
    return lrelu(a.x + r.x) * at.x + lrelu(a.y + r.y) * at.y
         + lrelu(a.z + r.z) * at.z + lrelu(a.w + r.w) * at.w;
}

__global__ __launch_bounds__(256) void node_agg_kernel(
    const float* __restrict__ xl, const float* __restrict__ xr,
    const float* __restrict__ xres, const float* __restrict__ att,
    const int* __restrict__ rowptr, const int* __restrict__ csr_src,
    float* __restrict__ out)
{
    int n = (blockIdx.x * blockDim.x + threadIdx.x) >> 5;
    int lane = threadIdx.x & 31;
    if (n >= NN) return;

    float4 at = *(const float4*)&att[lane * 4];
    float4 r  = *(const float4*)&xr[(size_t)n * 128 + lane * 4];

    int beg = rowptr[n];
    int end = rowptr[n + 1];

    float4 acc = make_float4(0.f, 0.f, 0.f, 0.f);
    float den = 0.f;

    int j = beg;
    for (; j + 1 < end; j += 2) {
        int s0 = __ldg(&csr_src[j]);
        int s1 = __ldg(&csr_src[j + 1]);
        float4 a0 = *(const float4*)&xl[(size_t)s0 * 128 + lane * 4];
        float4 a1 = *(const float4*)&xl[(size_t)s1 * 128 + lane * 4];

        float p0 = edge_logit(a0, r, at);
        float p1 = edge_logit(a1, r, at);

#pragma unroll
        for (int off = 16; off > 0; off >>= 1) {
            p0 += __shfl_xor_sync(0xFFFFFFFFu, p0, off);
            p1 += __shfl_xor_sync(0xFFFFFFFFu, p1, off);
        }
        float ex0 = __expf(p0);
        float ex1 = __expf(p1);

        acc.x += ex0 * a0.x + ex1 * a1.x;
        acc.y += ex0 * a0.y + ex1 * a1.y;
        acc.z += ex0 * a0.z + ex1 * a1.z;
        acc.w += ex0 * a0.w + ex1 * a1.w;
        den += ex0 + ex1;
    }
    if (j < end) {
        int s = __ldg(&csr_src[j]);
        float4 a = *(const float4*)&xl[(size_t)s * 128 + lane * 4];
        float p = edge_logit(a, r, at);
#pragma unroll
        for (int off = 16; off > 0; off >>= 1)
            p += __shfl_xor_sync(0xFFFFFFFFu, p, off);
        float ex = __expf(p);
        acc.x += ex * a.x; acc.y += ex * a.y;
        acc.z += ex * a.z; acc.w += ex * a.w;
        den += ex;
    }

    float inv = 1.f / fmaxf(den, 1e-16f);
    float4 rs = *(const float4*)&xres[(size_t)n * 128 + lane * 4];
    float4 o;
    o.x = fmaxf(acc.x * inv + rs.x, 0.f);
    o.y = fmaxf(acc.y * inv + rs.y, 0.f);
    o.z = fmaxf(acc.z * inv + rs.z, 0.f);
    o.w = fmaxf(acc.w * inv + rs.w, 0.f);
    *(float4*)&out[(size_t)n * 128 + lane * 4] = o;
}

// ---------------- host orchestration ----------------------------------------
extern "C" void kernel_launch(void* const* d_in, const int* in_sizes, int n_in,
                              void* d_out, int out_size)
{
    const float* x    = (const float*)d_in[0];
    const int* eidx   = (const int*)d_in[1];
    const float* Wl1  = (const float*)d_in[2];
    const float* Wr1  = (const float*)d_in[3];
    const float* att1 = (const float*)d_in[4];
    const float* Wres1= (const float*)d_in[5];
    const float* b1   = (const float*)d_in[6];
    const float* Wl2  = (const float*)d_in[7];
    const float* Wr2  = (const float*)d_in[8];
    const float* att2 = (const float*)d_in[9];
    const float* Wres2= (const float*)d_in[10];
    const float* b2   = (const float*)d_in[11];

    int E = in_sizes[1] / 2;
    const int* src = eidx;
    const int* dst = eidx + E;

    float *xl, *xr, *xres, *x1;
    int *rowptr, *cursor, *blocksums, *csr_src;
    cudaGetSymbolAddress((void**)&xl, g_xl);
    cudaGetSymbolAddress((void**)&xr, g_xr);
    cudaGetSymbolAddress((void**)&xres, g_xres);
    cudaGetSymbolAddress((void**)&x1, g_x1);
    cudaGetSymbolAddress((void**)&rowptr, g_rowptr);
    cudaGetSymbolAddress((void**)&cursor, g_cursor);
    cudaGetSymbolAddress((void**)&blocksums, g_blocksums);
    cudaGetSymbolAddress((void**)&csr_src, g_csr_src);

    static bool attr_set = false;
    if (!attr_set) {
        cudaFuncSetAttribute(gemm3_fused_kernel,
                             cudaFuncAttributeMaxDynamicSharedMemorySize,
                             SMEM_BYTES);
        attr_set = true;
    }

    // ---- CSR build (serial; fork experiment was net-negative) ----
    deg_zero_kernel<<<(NN + 255) / 256, 256>>>(rowptr);
    count_kernel<<<(E + 255) / 256, 256>>>(dst, rowptr, E);
    scan1_kernel<<<NSCAN_BLKS, SCAN_BLK>>>(rowptr, cursor, blocksums);
    scan2_kernel<<<1, 128>>>(blocksums);
    scan3_kernel<<<(NN + 255) / 256, 256>>>(cursor, blocksums, rowptr, cursor, E);
    scatter_kernel<<<(E + 255) / 256, 256>>>(src, dst, cursor, csr_src, E);

    int gemmBlocks = (NN + 127) / 128;
    int nodeBlocks = (NN * 32 + 255) / 256;

    // ---- layer 1 ----
    gemm3_fused_kernel<<<gemmBlocks, 256, SMEM_BYTES>>>(
        x, Wl1, Wr1, Wres1, b1, xl, xr, xres, NN);
    node_agg_kernel<<<nodeBlocks, 256>>>(xl, xr, xres, att1, rowptr, csr_src, x1);

    // ---- layer 2 ----
    gemm3_fused_kernel<<<gemmBlocks, 256, SMEM_BYTES>>>(
        x1, Wl2, Wr2, Wres2, b2, xl, xr, xres, NN);
    node_agg_kernel<<<nodeBlocks, 256>>>(xl, xr, xres, att2, rowptr, csr_src,
                                         (float*)d_out);
}

// round 17
// speedup vs baseline: 1.1468x; 1.0289x over previous
#include <cuda_runtime.h>
#include <math_constants.h>

#define NN 100000
#define C  128
#define EMAX_E 500000
#define NEG_SLOPE 0.2f
#define SCAN_BLK 1024
#define NSCAN_BLKS ((NN + SCAN_BLK - 1) / SCAN_BLK)   // 98

// ---------------- scratch (device globals, no allocations allowed) ----------
__device__ float g_xl[NN * C];
__device__ float g_xr[NN * C];
__device__ float g_xres[NN * C];
__device__ float g_x1[NN * C];
__device__ int   g_rowptr[NN + 1];
__device__ int   g_cursor[NN];
__device__ int   g_blocksums[SCAN_BLK];
__device__ int   g_csr_src[EMAX_E];

// ---------------- TF32 tensor-core GEMM ------------------------------------
// Block tile 128x128, K=128. A panel resident; B staged in 64-row half-panels
// so SMEM = 101.4KB -> 2 CTAs/SM. 8 warps, warp tile 64x32 (proven R11 shape).
__device__ __forceinline__ unsigned f2tf32(float f) {
    unsigned r;
    asm("cvt.rna.tf32.f32 %0, %1;" : "=r"(r) : "f"(f));
    return r;
}

#define PSTRIDE 132                          // 128 + 4 pad (words)
#define SMEM_WORDS ((128 + 64) * PSTRIDE)    // A panel 128xK + B half-panel 64xN
#define SMEM_BYTES (SMEM_WORDS * 4)          // 101376

__global__ __launch_bounds__(256, 2) void gemm3_fused_kernel(
    const float* __restrict__ X,
    const float* __restrict__ Wl, const float* __restrict__ Wr,
    const float* __restrict__ Wres, const float* __restrict__ bias,
    float* __restrict__ Yl, float* __restrict__ Yr, float* __restrict__ Yres,
    int M)
{
    extern __shared__ unsigned sh[];
    unsigned* As = sh;                  // [128][PSTRIDE]
    unsigned* Bs = sh + 128 * PSTRIDE;  // [64][PSTRIDE]

    const int tid  = threadIdx.x;
    const int lane = tid & 31;
    const int wid  = tid >> 5;
    const int wr   = wid >> 2;      // 0..1 -> M offset wr*64
    const int wc   = wid & 3;       // 0..3 -> N offset wc*32
    const int gp   = lane >> 2;
    const int tg   = lane & 3;
    const int m0   = blockIdx.x * 128;

    // ---- stage full A panel (128 rows x 128 k) as tf32 ----
#pragma unroll
    for (int i = tid; i < 128 * 32; i += 256) {
        int row = i >> 5, c4 = i & 31;
        int gm = m0 + row;
        float4 v = (gm < M) ? ((const float4*)(X + (size_t)gm * 128))[c4]
                            : make_float4(0.f, 0.f, 0.f, 0.f);
        unsigned* p = &As[row * PSTRIDE + c4 * 4];
        p[0] = f2tf32(v.x); p[1] = f2tf32(v.y);
        p[2] = f2tf32(v.z); p[3] = f2tf32(v.w);
    }

    for (int which = 0; which < 3; which++) {
        const float* W = (which == 0) ? Wl : (which == 1) ? Wr : Wres;
        float* Y       = (which == 0) ? Yl : (which == 1) ? Yr : Yres;

        float acc[4][4][4];
#pragma unroll
        for (int mi = 0; mi < 4; mi++)
#pragma unroll
            for (int ni = 0; ni < 4; ni++)
#pragma unroll
                for (int r = 0; r < 4; r++) acc[mi][ni][r] = 0.f;

#pragma unroll
        for (int half = 0; half < 2; half++) {
            __syncthreads();   // A ready / prior readers of Bs done
            // ---- stage B half-panel: k-rows [half*64, half*64+64) ----
#pragma unroll
            for (int i = tid; i < 64 * 32; i += 256) {
                int row = i >> 5, c4 = i & 31;
                float4 v = ((const float4*)(W + (half * 64 + row) * 128))[c4];
                unsigned* p = &Bs[row * PSTRIDE + c4 * 4];
                p[0] = f2tf32(v.x); p[1] = f2tf32(v.y);
                p[2] = f2tf32(v.z); p[3] = f2tf32(v.w);
            }
            __syncthreads();

#pragma unroll 4
            for (int kk0 = 0; kk0 < 64; kk0 += 8) {
                int kk = half * 64 + kk0;     // A k-index
                unsigned a[4][4];
#pragma unroll
                for (int mi = 0; mi < 4; mi++) {
                    int mrow = wr * 64 + mi * 16 + gp;
                    a[mi][0] = As[(mrow    ) * PSTRIDE + kk + tg    ];
                    a[mi][1] = As[(mrow + 8) * PSTRIDE + kk + tg    ];
                    a[mi][2] = As[(mrow    ) * PSTRIDE + kk + tg + 4];
                    a[mi][3] = As[(mrow + 8) * PSTRIDE + kk + tg + 4];
                }
                unsigned b[4][2];
#pragma unroll
                for (int ni = 0; ni < 4; ni++) {
                    int ncol = wc * 32 + ni * 8 + gp;
                    b[ni][0] = Bs[(kk0 + tg    ) * PSTRIDE + ncol];
                    b[ni][1] = Bs[(kk0 + tg + 4) * PSTRIDE + ncol];
                }
#pragma unroll
                for (int mi = 0; mi < 4; mi++)
#pragma unroll
                    for (int ni = 0; ni < 4; ni++) {
                        asm volatile(
                            "mma.sync.aligned.m16n8k8.row.col.f32.tf32.tf32.f32 "
                            "{%0,%1,%2,%3}, {%4,%5,%6,%7}, {%8,%9}, {%0,%1,%2,%3};"
                            : "+f"(acc[mi][ni][0]), "+f"(acc[mi][ni][1]),
                              "+f"(acc[mi][ni][2]), "+f"(acc[mi][ni][3])
                            : "r"(a[mi][0]), "r"(a[mi][1]), "r"(a[mi][2]), "r"(a[mi][3]),
                              "r"(b[ni][0]), "r"(b[ni][1]));
                    }
            }
        }

        // ---- epilogue ----
#pragma unroll
        for (int mi = 0; mi < 4; mi++) {
#pragma unroll
            for (int ni = 0; ni < 4; ni++) {
                int row = m0 + wr * 64 + mi * 16 + gp;
                int col = wc * 32 + ni * 8 + tg * 2;
                float b0 = 0.f, b1 = 0.f;
                if (which == 2 && bias) { b0 = bias[col]; b1 = bias[col + 1]; }
                if (row < M) {
                    float2 v = make_float2(acc[mi][ni][0] + b0,
                                           acc[mi][ni][1] + b1);
                    *(float2*)&Y[(size_t)row * 128 + col] = v;
                }
                if (row + 8 < M) {
                    float2 v = make_float2(acc[mi][ni][2] + b0,
                                           acc[mi][ni][3] + b1);
                    *(float2*)&Y[(size_t)(row + 8) * 128 + col] = v;
                }
            }
        }
    }
}

// ================= CSR construction (once per call, shared by layers) =======
__global__ void deg_zero_kernel(int* __restrict__ deg)
{
    int i = blockIdx.x * blockDim.x + threadIdx.x;
    if (i < NN) deg[i] = 0;
}

__global__ void count_kernel(const int* __restrict__ dst, int* __restrict__ deg,
                             int E)
{
    int i = blockIdx.x * blockDim.x + threadIdx.x;
    if (i < E) atomicAdd(&deg[dst[i]], 1);
}

__global__ __launch_bounds__(SCAN_BLK) void scan1_kernel(
    const int* __restrict__ deg, int* __restrict__ pref,
    int* __restrict__ blockSums)
{
    __shared__ int sm[SCAN_BLK];
    int tid = threadIdx.x;
    int i = blockIdx.x * SCAN_BLK + tid;
    int v = (i < NN) ? deg[i] : 0;
    sm[tid] = v;
    __syncthreads();
#pragma unroll
    for (int off = 1; off < SCAN_BLK; off <<= 1) {
        int t = (tid >= off) ? sm[tid - off] : 0;
        __syncthreads();
        sm[tid] += t;
        __syncthreads();
    }
    if (i < NN) pref[i] = sm[tid] - v;
    if (tid == SCAN_BLK - 1) blockSums[blockIdx.x] = sm[tid];
}

// scan2+scan3 fused: each block redundantly scans the 98 block sums (392B)
// in SMEM, then applies offsets. Arithmetic identical to scan2;scan3.
__global__ __launch_bounds__(SCAN_BLK) void scan23_kernel(
    const int* __restrict__ pref, const int* __restrict__ blockSums,
    int* __restrict__ rowptr, int* __restrict__ cursor, int E)
{
    __shared__ int offs[NSCAN_BLKS];
    int tid = threadIdx.x;
    if (tid == 0) {
        int run = 0;
        for (int b = 0; b < NSCAN_BLKS; b++) {
            offs[b] = run;
            run += blockSums[b];
        }
    }
    __syncthreads();
    int i = blockIdx.x * SCAN_BLK + tid;
    if (i < NN) {
        int r = pref[i] + offs[i >> 10];
        rowptr[i] = r;
        cursor[i] = r;
    }
    if (i == 0) rowptr[NN] = E;
}

__global__ void scatter_kernel(const int* __restrict__ src,
                               const int* __restrict__ dst,
                               int* __restrict__ cursor,
                               int* __restrict__ csr_src, int E)
{
    int i = blockIdx.x * blockDim.x + threadIdx.x;
    if (i < E) {
        int p = atomicAdd(&cursor[dst[i]], 1);
        csr_src[p] = src[i];
    }
}

// ================= fused node aggregation (R11/R16 proven version) ==========
__device__ __forceinline__ float lrelu(float v)
{
    return v > 0.f ? v : NEG_SLOPE * v;
}

__device__ __forceinline__ float edge_logit(float4 a, float4 r, float4 at)
{
    return lrelu(a.x + r.x) * at.x + lrelu(a.y + r.y) * at.y
         + lrelu(a.z + r.z) * at.z + lrelu(a.w + r.w) * at.w;
}

__global__ __launch_bounds__(256) void node_agg_kernel(
    const float* __restrict__ xl, const float* __restrict__ xr,
    const float* __restrict__ xres, const float* __restrict__ att,
    const int* __restrict__ rowptr, const int* __restrict__ csr_src,
    float* __restrict__ out)
{
    int n = (blockIdx.x * blockDim.x + threadIdx.x) >> 5;
    int lane = threadIdx.x & 31;
    if (n >= NN) return;

    float4 at = *(const float4*)&att[lane * 4];
    float4 r  = *(const float4*)&xr[(size_t)n * 128 + lane * 4];

    int beg = rowptr[n];
    int end = rowptr[n + 1];

    float4 acc = make_float4(0.f, 0.f, 0.f, 0.f);
    float den = 0.f;

    int j = beg;
    for (; j + 1 < end; j += 2) {
        int s0 = __ldg(&csr_src[j]);
        int s1 = __ldg(&csr_src[j + 1]);
        float4 a0 = *(const float4*)&xl[(size_t)s0 * 128 + lane * 4];
        float4 a1 = *(const float4*)&xl[(size_t)s1 * 128 + lane * 4];

        float p0 = edge_logit(a0, r, at);
        float p1 = edge_logit(a1, r, at);

#pragma unroll
        for (int off = 16; off > 0; off >>= 1) {
            p0 += __shfl_xor_sync(0xFFFFFFFFu, p0, off);
            p1 += __shfl_xor_sync(0xFFFFFFFFu, p1, off);
        }
        float ex0 = __expf(p0);
        float ex1 = __expf(p1);

        acc.x += ex0 * a0.x + ex1 * a1.x;
        acc.y += ex0 * a0.y + ex1 * a1.y;
        acc.z += ex0 * a0.z + ex1 * a1.z;
        acc.w += ex0 * a0.w + ex1 * a1.w;
        den += ex0 + ex1;
    }
    if (j < end) {
        int s = __ldg(&csr_src[j]);
        float4 a = *(const float4*)&xl[(size_t)s * 128 + lane * 4];
        float p = edge_logit(a, r, at);
#pragma unroll
        for (int off = 16; off > 0; off >>= 1)
            p += __shfl_xor_sync(0xFFFFFFFFu, p, off);
        float ex = __expf(p);
        acc.x += ex * a.x; acc.y += ex * a.y;
        acc.z += ex * a.z; acc.w += ex * a.w;
        den += ex;
    }

    float inv = 1.f / fmaxf(den, 1e-16f);
    float4 rs = *(const float4*)&xres[(size_t)n * 128 + lane * 4];
    float4 o;
    o.x = fmaxf(acc.x * inv + rs.x, 0.f);
    o.y = fmaxf(acc.y * inv + rs.y, 0.f);
    o.z = fmaxf(acc.z * inv + rs.z, 0.f);
    o.w = fmaxf(acc.w * inv + rs.w, 0.f);
    *(float4*)&out[(size_t)n * 128 + lane * 4] = o;
}

// ---------------- host orchestration ----------------------------------------
extern "C" void kernel_launch(void* const* d_in, const int* in_sizes, int n_in,
                              void* d_out, int out_size)
{
    const float* x    = (const float*)d_in[0];
    const int* eidx   = (const int*)d_in[1];
    const float* Wl1  = (const float*)d_in[2];
    const float* Wr1  = (const float*)d_in[3];
    const float* att1 = (const float*)d_in[4];
    const float* Wres1= (const float*)d_in[5];
    const float* b1   = (const float*)d_in[6];
    const float* Wl2  = (const float*)d_in[7];
    const float* Wr2  = (const float*)d_in[8];
    const float* att2 = (const float*)d_in[9];
    const float* Wres2= (const float*)d_in[10];
    const float* b2   = (const float*)d_in[11];

    int E = in_sizes[1] / 2;
    const int* src = eidx;
    const int* dst = eidx + E;

    float *xl, *xr, *xres, *x1;
    int *rowptr, *cursor, *blocksums, *csr_src;
    cudaGetSymbolAddress((void**)&xl, g_xl);
    cudaGetSymbolAddress((void**)&xr, g_xr);
    cudaGetSymbolAddress((void**)&xres, g_xres);
    cudaGetSymbolAddress((void**)&x1, g_x1);
    cudaGetSymbolAddress((void**)&rowptr, g_rowptr);
    cudaGetSymbolAddress((void**)&cursor, g_cursor);
    cudaGetSymbolAddress((void**)&blocksums, g_blocksums);
    cudaGetSymbolAddress((void**)&csr_src, g_csr_src);

    static cudaStream_t s_side = nullptr;
    static cudaEvent_t ev_fork = nullptr, ev_join = nullptr;
    if (s_side == nullptr) {
        cudaStreamCreateWithFlags(&s_side, cudaStreamNonBlocking);
        cudaEventCreateWithFlags(&ev_fork, cudaEventDisableTiming);
        cudaEventCreateWithFlags(&ev_join, cudaEventDisableTiming);
        cudaFuncSetAttribute(gemm3_fused_kernel,
                             cudaFuncAttributeMaxDynamicSharedMemorySize,
                             SMEM_BYTES);
    }

    // ---- fork: CSR build on side stream, layer-1 GEMM on main stream ----
    cudaEventRecord(ev_fork, 0);
    cudaStreamWaitEvent(s_side, ev_fork, 0);

    deg_zero_kernel<<<(NN + 255) / 256, 256, 0, s_side>>>(rowptr);
    count_kernel<<<(E + 255) / 256, 256, 0, s_side>>>(dst, rowptr, E);
    scan1_kernel<<<NSCAN_BLKS, SCAN_BLK, 0, s_side>>>(rowptr, cursor, blocksums);
    scan23_kernel<<<NSCAN_BLKS, SCAN_BLK, 0, s_side>>>(cursor, blocksums,
                                                       rowptr, cursor, E);
    scatter_kernel<<<(E + 255) / 256, 256, 0, s_side>>>(src, dst, cursor,
                                                        csr_src, E);
    cudaEventRecord(ev_join, s_side);

    int gemmBlocks = (NN + 127) / 128;
    int nodeBlocks = (NN * 32 + 255) / 256;

    // ---- layer 1 GEMM (main stream, concurrent with CSR) ----
    gemm3_fused_kernel<<<gemmBlocks, 256, SMEM_BYTES>>>(
        x, Wl1, Wr1, Wres1, b1, xl, xr, xres, NN);

    // ---- join: aggregation needs CSR ----
    cudaStreamWaitEvent(0, ev_join, 0);
    node_agg_kernel<<<nodeBlocks, 256>>>(xl, xr, xres, att1, rowptr, csr_src, x1);

    // ---- layer 2 ----
    gemm3_fused_kernel<<<gemmBlocks, 256, SMEM_BYTES>>>(
        x1, Wl2, Wr2, Wres2, b2, xl, xr, xres, NN);
    node_agg_kernel<<<nodeBlocks, 256>>>(xl, xr, xres, att2, rowptr, csr_src,
                                         (float*)d_out);
}